// round 2
// baseline (speedup 1.0000x reference)
#include <cuda_runtime.h>
#include <math.h>

#define NN 4096      // nodes
#define FIN 4096     // input features
#define HD 128       // hidden / emb
#define RR 8         // relations
#define GGRP 3       // groups
#define NE 65536     // edges
#define NCOLS 1152   // 8*128 + 128 (W_r's concat + root)
#define LAMDA 0.01f
#define EPSN 1e-5f

// ---------------- scratch (static device allocations are allowed) -------------
__device__ float g_Bpack[FIN * NCOLS];         // packed B for GEMM (reused layer1/2)
__device__ float g_Y[NN * NCOLS];              // GEMM output (reused layer1/2)
__device__ float g_agg[NN * RR * HD];          // per (dst, r) aggregated transformed feats
__device__ int   g_cnt[NN * RR];               // edge counts per (dst, r)
__device__ float g_h[NN * HD];                 // layer-1 output
__device__ float g_h2[NN * HD];                // post-DGN+relu
__device__ float g_s[NN * GGRP];               // softmax scores
__device__ float g_sum[GGRP * HD];
__device__ float g_sq[GGRP * HD];
__device__ float g_a[GGRP * HD];               // bn_w / sigma
__device__ float g_d[GGRP * HD];               // bn_b - mean * a

// ---------------- utility kernels --------------------------------------------
__global__ void zero_f(float* p, int n) {
    int i = blockIdx.x * 256 + threadIdx.x;
    if (i < n) p[i] = 0.f;
}
__global__ void zero_i(int* p, int n) {
    int i = blockIdx.x * 256 + threadIdx.x;
    if (i < n) p[i] = 0;
}

__global__ void count_edges(const int* __restrict__ ei, const int* __restrict__ et) {
    int e = blockIdx.x * 256 + threadIdx.x;
    if (e < NE) atomicAdd(&g_cnt[ei[NE + e] * RR + et[e]], 1);
}

// pack W1[R, FIN, HD] + root1[FIN, HD] into row-major [FIN, NCOLS]
__global__ void pack_B1(const float* __restrict__ W1, const float* __restrict__ root1) {
    int f = blockIdx.y;
    int c = blockIdx.x * 128 + threadIdx.x;
    float v;
    if (c < RR * HD) v = W1[(((c >> 7) * FIN) + f) * HD + (c & 127)];
    else             v = root1[f * HD + (c - RR * HD)];
    g_Bpack[f * NCOLS + c] = v;
}

// pack W2[R, HD, HD] + root2[HD, HD] into row-major [HD, NCOLS]
__global__ void pack_B2(const float* __restrict__ W2, const float* __restrict__ root2) {
    int k = blockIdx.y;
    int c = blockIdx.x * 128 + threadIdx.x;
    float v;
    if (c < RR * HD) v = W2[(((c >> 7) * HD) + k) * HD + (c & 127)];
    else             v = root2[k * HD + (c - RR * HD)];
    g_Bpack[k * NCOLS + c] = v;
}

// ---------------- SGEMM: C[M,N] = A[M,K] @ B[K,N], all row-major --------------
// 128x128 tile, BK=16, 256 threads, 8x8 per thread, double-buffered smem.
#define BM 128
#define BN 128
#define BK 16

__global__ __launch_bounds__(256, 2) void sgemm_k(
    const float* __restrict__ A, const float* __restrict__ B, float* __restrict__ C,
    int M, int N, int K)
{
    __shared__ __align__(16) float As[2][BK][BM];
    __shared__ __align__(16) float Bs[2][BK][BN];

    const int tid = threadIdx.x;
    const int tx = tid & 15;
    const int ty = tid >> 4;
    const int m0 = blockIdx.y * BM;
    const int n0 = blockIdx.x * BN;

    // global load base pointers (this thread's 2 float4's of A, 2 of B per tile)
    const int aRow = tid >> 2;          // 0..63
    const int aKq  = (tid & 3) * 4;     // k offset 0,4,8,12
    const int bKr  = tid >> 5;          // 0..7
    const int bC   = (tid & 31) * 4;    // 0..124
    const float* Ap = A + (size_t)(m0 + aRow) * K + aKq;
    const float* Bp = B + (size_t)bKr * N + n0 + bC;

    float acc[8][8];
#pragma unroll
    for (int i = 0; i < 8; i++)
#pragma unroll
        for (int j = 0; j < 8; j++) acc[i][j] = 0.f;

    // preload tile 0
    float4 a0g = *(const float4*)(Ap);
    float4 a1g = *(const float4*)(Ap + (size_t)64 * K);
    float4 b0g = *(const float4*)(Bp);
    float4 b1g = *(const float4*)(Bp + (size_t)8 * N);
    {
        As[0][aKq + 0][aRow] = a0g.x; As[0][aKq + 1][aRow] = a0g.y;
        As[0][aKq + 2][aRow] = a0g.z; As[0][aKq + 3][aRow] = a0g.w;
        As[0][aKq + 0][aRow + 64] = a1g.x; As[0][aKq + 1][aRow + 64] = a1g.y;
        As[0][aKq + 2][aRow + 64] = a1g.z; As[0][aKq + 3][aRow + 64] = a1g.w;
        *(float4*)&Bs[0][bKr][bC] = b0g;
        *(float4*)&Bs[0][bKr + 8][bC] = b1g;
    }
    __syncthreads();

    const int ntiles = K / BK;
    int buf = 0;
    for (int t = 1; t < ntiles; ++t) {
        const float* Ak = Ap + t * BK;
        const float* Bk = Bp + (size_t)t * BK * N;
        a0g = *(const float4*)(Ak);
        a1g = *(const float4*)(Ak + (size_t)64 * K);
        b0g = *(const float4*)(Bk);
        b1g = *(const float4*)(Bk + (size_t)8 * N);

#pragma unroll
        for (int kk = 0; kk < BK; ++kk) {
            float4 av0 = *(const float4*)&As[buf][kk][ty * 8];
            float4 av1 = *(const float4*)&As[buf][kk][ty * 8 + 4];
            float4 bv0 = *(const float4*)&Bs[buf][kk][tx * 8];
            float4 bv1 = *(const float4*)&Bs[buf][kk][tx * 8 + 4];
            float av[8] = {av0.x, av0.y, av0.z, av0.w, av1.x, av1.y, av1.z, av1.w};
            float bv[8] = {bv0.x, bv0.y, bv0.z, bv0.w, bv1.x, bv1.y, bv1.z, bv1.w};
#pragma unroll
            for (int i = 0; i < 8; i++)
#pragma unroll
                for (int j = 0; j < 8; j++) acc[i][j] += av[i] * bv[j];
        }

        int nb = buf ^ 1;
        As[nb][aKq + 0][aRow] = a0g.x; As[nb][aKq + 1][aRow] = a0g.y;
        As[nb][aKq + 2][aRow] = a0g.z; As[nb][aKq + 3][aRow] = a0g.w;
        As[nb][aKq + 0][aRow + 64] = a1g.x; As[nb][aKq + 1][aRow + 64] = a1g.y;
        As[nb][aKq + 2][aRow + 64] = a1g.z; As[nb][aKq + 3][aRow + 64] = a1g.w;
        *(float4*)&Bs[nb][bKr][bC] = b0g;
        *(float4*)&Bs[nb][bKr + 8][bC] = b1g;
        __syncthreads();
        buf = nb;
    }

#pragma unroll
    for (int kk = 0; kk < BK; ++kk) {
        float4 av0 = *(const float4*)&As[buf][kk][ty * 8];
        float4 av1 = *(const float4*)&As[buf][kk][ty * 8 + 4];
        float4 bv0 = *(const float4*)&Bs[buf][kk][tx * 8];
        float4 bv1 = *(const float4*)&Bs[buf][kk][tx * 8 + 4];
        float av[8] = {av0.x, av0.y, av0.z, av0.w, av1.x, av1.y, av1.z, av1.w};
        float bv[8] = {bv0.x, bv0.y, bv0.z, bv0.w, bv1.x, bv1.y, bv1.z, bv1.w};
#pragma unroll
        for (int i = 0; i < 8; i++)
#pragma unroll
            for (int j = 0; j < 8; j++) acc[i][j] += av[i] * bv[j];
    }

#pragma unroll
    for (int i = 0; i < 8; i++) {
        float4 c0 = {acc[i][0], acc[i][1], acc[i][2], acc[i][3]};
        float4 c1 = {acc[i][4], acc[i][5], acc[i][6], acc[i][7]};
        float* Cr = C + (size_t)(m0 + ty * 8 + i) * N + n0 + tx * 8;
        *(float4*)(Cr) = c0;
        *(float4*)(Cr + 4) = c1;
    }
}

// ---------------- edge scatter (transform-then-aggregate) ---------------------
__global__ void scatter_agg(const float* __restrict__ Y,
                            const int* __restrict__ ei, const int* __restrict__ et) {
    int idx = blockIdx.x * 256 + threadIdx.x;
    if (idx >= NE * HD) return;
    int e = idx >> 7, hh = idx & 127;
    int src = ei[e];
    int dst = ei[NE + e];
    int r = et[e];
    float v = Y[(size_t)src * NCOLS + r * HD + hh];
    atomicAdd(&g_agg[((size_t)dst * RR + r) * HD + hh], v);
}

__global__ void combine1(const float* __restrict__ b1) {
    int idx = blockIdx.x * 256 + threadIdx.x;  // NN*HD
    int n = idx >> 7, hh = idx & 127;
    float v = b1[hh] + g_Y[(size_t)n * NCOLS + RR * HD + hh];
#pragma unroll
    for (int r = 0; r < RR; r++) {
        float c = (float)g_cnt[n * RR + r];
        v += g_agg[((size_t)n * RR + r) * HD + hh] / fmaxf(c, 1.f);
    }
    g_h[idx] = v;
}

// ---------------- DiffGroupNorm pieces ----------------------------------------
__global__ void softmax_s(const float* __restrict__ lin_w, const float* __restrict__ lin_b) {
    int n = blockIdx.x;
    int t = threadIdx.x;  // 128
    float hv = g_h[n * HD + t];
    float p0 = hv * lin_w[t * GGRP + 0];
    float p1 = hv * lin_w[t * GGRP + 1];
    float p2 = hv * lin_w[t * GGRP + 2];
#pragma unroll
    for (int o = 16; o; o >>= 1) {
        p0 += __shfl_down_sync(0xffffffffu, p0, o);
        p1 += __shfl_down_sync(0xffffffffu, p1, o);
        p2 += __shfl_down_sync(0xffffffffu, p2, o);
    }
    __shared__ float sm[4][3];
    if ((t & 31) == 0) { sm[t >> 5][0] = p0; sm[t >> 5][1] = p1; sm[t >> 5][2] = p2; }
    __syncthreads();
    if (t == 0) {
        float l0 = lin_b[0], l1 = lin_b[1], l2 = lin_b[2];
        for (int w = 0; w < 4; w++) { l0 += sm[w][0]; l1 += sm[w][1]; l2 += sm[w][2]; }
        float mx = fmaxf(l0, fmaxf(l1, l2));
        float e0 = expf(l0 - mx), e1 = expf(l1 - mx), e2 = expf(l2 - mx);
        float inv = 1.f / (e0 + e1 + e2);
        g_s[n * 3 + 0] = e0 * inv;
        g_s[n * 3 + 1] = e1 * inv;
        g_s[n * 3 + 2] = e2 * inv;
    }
}

__global__ void stats_k() {
    int t = threadIdx.x;          // h: 0..127
    int chunk = blockIdx.x;       // 128 blocks x 32 rows
    float sum0 = 0, sum1 = 0, sum2 = 0, sq0 = 0, sq1 = 0, sq2 = 0;
    for (int i = 0; i < 32; i++) {
        int n = chunk * 32 + i;
        float hv = g_h[n * HD + t];
        float s0 = g_s[n * 3 + 0], s1 = g_s[n * 3 + 1], s2 = g_s[n * 3 + 2];
        float v0 = s0 * hv, v1 = s1 * hv, v2 = s2 * hv;
        sum0 += v0; sq0 += v0 * v0;
        sum1 += v1; sq1 += v1 * v1;
        sum2 += v2; sq2 += v2 * v2;
    }
    atomicAdd(&g_sum[0 * HD + t], sum0);
    atomicAdd(&g_sum[1 * HD + t], sum1);
    atomicAdd(&g_sum[2 * HD + t], sum2);
    atomicAdd(&g_sq[0 * HD + t], sq0);
    atomicAdd(&g_sq[1 * HD + t], sq1);
    atomicAdd(&g_sq[2 * HD + t], sq2);
}

__global__ void stats_final(const float* __restrict__ bn_w, const float* __restrict__ bn_b) {
    int i = blockIdx.x * 128 + threadIdx.x;  // 384
    if (i < GGRP * HD) {
        const float invN = 1.f / (float)NN;
        float mean = g_sum[i] * invN;
        float var = g_sq[i] * invN - mean * mean;
        float a = bn_w[i] / sqrtf(var + EPSN);
        g_a[i] = a;
        g_d[i] = bn_b[i] - mean * a;
    }
}

__global__ void h2_k() {
    int idx = blockIdx.x * 256 + threadIdx.x;  // NN*HD
    int n = idx >> 7, hh = idx & 127;
    float hv = g_h[idx];
    float s0 = g_s[n * 3 + 0], s1 = g_s[n * 3 + 1], s2 = g_s[n * 3 + 2];
    float aa = s0 * g_a[hh] + s1 * g_a[HD + hh] + s2 * g_a[2 * HD + hh];
    float cc = g_d[hh] + g_d[HD + hh] + g_d[2 * HD + hh];
    float v = hv * (1.f + LAMDA * aa) + LAMDA * cc;
    g_h2[idx] = fmaxf(v, 0.f);
}

__global__ void combine2(const float* __restrict__ b2, float* __restrict__ out) {
    int idx = blockIdx.x * 256 + threadIdx.x;  // NN*HD
    int n = idx >> 7, hh = idx & 127;
    float v = b2[hh] + g_Y[(size_t)n * NCOLS + RR * HD + hh];
#pragma unroll
    for (int r = 0; r < RR; r++) {
        float c = (float)g_cnt[n * RR + r];
        v += g_agg[((size_t)n * RR + r) * HD + hh] / fmaxf(c, 1.f);
    }
    out[idx] = v;
}

// ---------------- launch ------------------------------------------------------
extern "C" void kernel_launch(void* const* d_in, const int* in_sizes, int n_in,
                              void* d_out, int out_size) {
    const float* x      = (const float*)d_in[0];
    const int*   ei     = (const int*)d_in[1];
    const int*   et     = (const int*)d_in[2];
    const float* W1     = (const float*)d_in[3];
    const float* root1  = (const float*)d_in[4];
    const float* b1     = (const float*)d_in[5];
    const float* lin_w  = (const float*)d_in[6];
    const float* lin_b  = (const float*)d_in[7];
    const float* bn_w   = (const float*)d_in[8];
    const float* bn_b   = (const float*)d_in[9];
    const float* W2     = (const float*)d_in[10];
    const float* root2  = (const float*)d_in[11];
    const float* b2     = (const float*)d_in[12];
    float* out = (float*)d_out;

    float *Bp, *Yp, *aggp, *sump, *sqp, *h2p;
    int* cntp;
    cudaGetSymbolAddress((void**)&Bp, g_Bpack);
    cudaGetSymbolAddress((void**)&Yp, g_Y);
    cudaGetSymbolAddress((void**)&aggp, g_agg);
    cudaGetSymbolAddress((void**)&cntp, g_cnt);
    cudaGetSymbolAddress((void**)&sump, g_sum);
    cudaGetSymbolAddress((void**)&sqp, g_sq);
    cudaGetSymbolAddress((void**)&h2p, g_h2);

    const int AGG_N = NN * RR * HD;

    // zero scratch
    zero_f<<<(AGG_N + 255) / 256, 256>>>(aggp, AGG_N);
    zero_i<<<(NN * RR + 255) / 256, 256>>>(cntp, NN * RR);
    zero_f<<<2, 256>>>(sump, GGRP * HD);
    zero_f<<<2, 256>>>(sqp, GGRP * HD);

    // edge counts
    count_edges<<<NE / 256, 256>>>(ei, et);

    // layer 1: Y1 = x @ [W1_r ... | root1]
    {
        dim3 g(NCOLS / 128, NN);
        pack_B1<<<g, 128>>>(W1, root1);
    }
    {
        dim3 grid(NCOLS / BN, NN / BM);
        sgemm_k<<<grid, 256>>>(x, Bp, Yp, NN, NCOLS, FIN);
    }
    scatter_agg<<<(NE * HD) / 256, 256>>>(Yp, ei, et);
    combine1<<<(NN * HD) / 256, 256>>>(b1);

    // DiffGroupNorm + relu
    softmax_s<<<NN, 128>>>(lin_w, lin_b);
    stats_k<<<128, 128>>>();
    stats_final<<<3, 128>>>(bn_w, bn_b);
    h2_k<<<(NN * HD) / 256, 256>>>();

    // layer 2: Y2 = h2 @ [W2_r ... | root2]
    {
        dim3 g(NCOLS / 128, HD);
        pack_B2<<<g, 128>>>(W2, root2);
    }
    {
        dim3 grid(NCOLS / BN, NN / BM);
        sgemm_k<<<grid, 256>>>(h2p, Bp, Yp, NN, NCOLS, HD);
    }
    zero_f<<<(AGG_N + 255) / 256, 256>>>(aggp, AGG_N);
    scatter_agg<<<(NE * HD) / 256, 256>>>(Yp, ei, et);
    combine2<<<(NN * HD) / 256, 256>>>(b2, out);
}

// round 4
// speedup vs baseline: 3.3704x; 3.3704x over previous
#include <cuda_runtime.h>
#include <cuda_fp16.h>
#include <math.h>
#include <stdint.h>

#define NN 4096      // nodes
#define FIN 4096     // input features
#define HD 128       // hidden / emb
#define RR 8         // relations
#define GGRP 3       // groups
#define NE 65536     // edges
#define NCOLS 1152   // 8*128 + 128
#define LAMDA 0.01f
#define EPSN 1e-5f

// GEMM tiling
#define BMT 128
#define BNT 128
#define BKT 64
#define STG 3
#define STAGE_B (BMT * BKT * 2 + BNT * BKT * 2)   // 32768 bytes per stage
#define GEMM_SMEM (STG * STAGE_B + 128)

// ---------------- scratch ------------------------------------------------------
__device__ __align__(16) __half g_Ah[(size_t)NN * FIN];      // x as fp16
__device__ __align__(16) __half g_Bth[(size_t)NCOLS * FIN];  // B^T packed [n, k] fp16
__device__ __align__(16) __half g_h2h[NN * HD];              // post-DGN+relu fp16
__device__ float g_Y[(size_t)NN * NCOLS];
__device__ float g_agg[(size_t)NN * RR * HD];
__device__ int   g_cnt[NN * RR];
__device__ float g_h[NN * HD];
__device__ float g_s[NN * GGRP];
__device__ float g_sum[GGRP * HD];
__device__ float g_sq[GGRP * HD];
__device__ float g_a[GGRP * HD];
__device__ float g_d[GGRP * HD];

// ---------------- PTX helpers --------------------------------------------------
__device__ __forceinline__ uint32_t smem_u32(const void* p) {
    uint32_t a;
    asm("{ .reg .u64 t; cvta.to.shared.u64 t, %1; cvt.u32.u64 %0, t; }" : "=r"(a) : "l"(p));
    return a;
}
__device__ __forceinline__ void cp16(uint32_t d, const void* s) {
    asm volatile("cp.async.cg.shared.global [%0], [%1], 16;" :: "r"(d), "l"(s));
}
__device__ __forceinline__ void ldsm4(uint32_t& r0, uint32_t& r1, uint32_t& r2, uint32_t& r3,
                                      uint32_t a) {
    asm volatile("ldmatrix.sync.aligned.m8n8.x4.shared.b16 {%0,%1,%2,%3}, [%4];"
        : "=r"(r0), "=r"(r1), "=r"(r2), "=r"(r3) : "r"(a));
}
__device__ __forceinline__ void mma16816(float* d, const uint32_t* a, uint32_t b0, uint32_t b1) {
    asm volatile("mma.sync.aligned.m16n8k16.row.col.f32.f16.f16.f32 "
        "{%0,%1,%2,%3}, {%4,%5,%6,%7}, {%8,%9}, {%0,%1,%2,%3};"
        : "+f"(d[0]), "+f"(d[1]), "+f"(d[2]), "+f"(d[3])
        : "r"(a[0]), "r"(a[1]), "r"(a[2]), "r"(a[3]), "r"(b0), "r"(b1));
}

// ---------------- HMMA GEMM: C[M,1152] = A[M,K]fp16 @ Bt[1152,K]fp16^T ----------
__global__ __launch_bounds__(256, 1) void gemm_hmma(
    const __half* __restrict__ A, const __half* __restrict__ Bt,
    float* __restrict__ C, int K)
{
    extern __shared__ char smem_raw[];
    uint32_t sb = (smem_u32(smem_raw) + 127u) & ~127u;
    const int tid = threadIdx.x;
    const int lane = tid & 31;
    const int w = tid >> 5;
    const int m0 = blockIdx.y * BMT;
    const int n0 = blockIdx.x * BNT;
    const int wm = (w >> 2) * 64;     // warp tile 64x32, 2x4 warp grid
    const int wn = (w & 3) * 32;
    const int T = K >> 6;

    const int r7 = lane & 7;
    const int mat01 = (lane >> 3) & 1;
    const int mat2 = (lane >> 4) & 1;

    float acc[4][4][4];
#pragma unroll
    for (int i = 0; i < 4; i++)
#pragma unroll
        for (int j = 0; j < 4; j++)
#pragma unroll
            for (int c = 0; c < 4; c++) acc[i][j][c] = 0.f;

    auto ld_stage = [&](int buf, int t) {
        uint32_t base = sb + buf * STAGE_B;
        int k0 = t << 6;
#pragma unroll
        for (int i = 0; i < 4; i++) {
            int idx = tid + i * 256;         // 1024 16B-units per operand tile
            int row = idx >> 3;
            int u = idx & 7;
            int su = u ^ (row & 7);
            cp16(base + row * 128 + su * 16,
                 A + (size_t)(m0 + row) * K + k0 + u * 8);
            cp16(base + BMT * BKT * 2 + row * 128 + su * 16,
                 Bt + (size_t)(n0 + row) * K + k0 + u * 8);
        }
    };

    for (int p = 0; p < STG - 1; p++) {
        if (p < T) ld_stage(p, p);
        asm volatile("cp.async.commit_group;");
    }

    for (int t = 0; t < T; t++) {
        asm volatile("cp.async.wait_group %0;" :: "n"(STG - 2));
        __syncthreads();   // stage t ready; compute of t-1 done (buffer reuse safe)

        int pf = t + STG - 1;
        if (pf < T) ld_stage(pf % STG, pf);
        asm volatile("cp.async.commit_group;");

        uint32_t Ab = sb + (t % STG) * STAGE_B;
        uint32_t Bb = Ab + BMT * BKT * 2;

#pragma unroll
        for (int ks = 0; ks < 4; ks++) {
            const int u = ks * 2 + mat2;
            const int su16 = ((u ^ r7) * 16);

            uint32_t a[4][4];
#pragma unroll
            for (int i = 0; i < 4; i++) {
                int mrow = wm + i * 16 + mat01 * 8 + r7;
                ldsm4(a[i][0], a[i][1], a[i][2], a[i][3], Ab + mrow * 128 + su16);
            }
            uint32_t b[2][4];
#pragma unroll
            for (int j2 = 0; j2 < 2; j2++) {
                int nrow = wn + j2 * 16 + mat01 * 8 + r7;
                ldsm4(b[j2][0], b[j2][1], b[j2][2], b[j2][3], Bb + nrow * 128 + su16);
            }
#pragma unroll
            for (int i = 0; i < 4; i++)
#pragma unroll
                for (int j = 0; j < 4; j++) {
                    // n-block j: regs {b[j>>1][j&1], b[j>>1][(j&1)+2]}
                    mma16816(acc[i][j], a[i], b[j >> 1][j & 1], b[j >> 1][(j & 1) + 2]);
                }
        }
    }

    // epilogue: direct fp32 stores
#pragma unroll
    for (int i = 0; i < 4; i++)
#pragma unroll
        for (int j = 0; j < 4; j++) {
            int m = m0 + wm + i * 16 + (lane >> 2);
            int n = n0 + wn + j * 8 + (lane & 3) * 2;
            float* p = C + (size_t)m * NCOLS + n;
            float2 v0 = make_float2(acc[i][j][0], acc[i][j][1]);
            float2 v1 = make_float2(acc[i][j][2], acc[i][j][3]);
            *(float2*)p = v0;
            *(float2*)(p + (size_t)8 * NCOLS) = v1;
        }
}

// ---------------- conversion / packing -----------------------------------------
__global__ void conv_x(const float* __restrict__ x) {
    size_t i = (size_t)blockIdx.x * 256 + threadIdx.x;   // NN*FIN/4
    float4 v = ((const float4*)x)[i];
    __half2* dst = (__half2*)g_Ah;
    dst[i * 2 + 0] = __floats2half2_rn(v.x, v.y);
    dst[i * 2 + 1] = __floats2half2_rn(v.z, v.w);
}

// Bt1[n, k] = (n<1024) ? W1[n>>7][k][n&127] : root1[k][n-1024]
__global__ void pack_Bt1(const float* __restrict__ W1, const float* __restrict__ root1) {
    int k = blockIdx.x * 256 + threadIdx.x;
    int n = blockIdx.y;
    float v;
    if (n < RR * HD) v = W1[((size_t)(n >> 7) * FIN + k) * HD + (n & 127)];
    else             v = root1[(size_t)k * HD + (n - RR * HD)];
    g_Bth[(size_t)n * FIN + k] = __float2half_rn(v);
}

// Bt2[n, k] (stride HD)
__global__ void pack_Bt2(const float* __restrict__ W2, const float* __restrict__ root2) {
    int k = threadIdx.x;   // 0..127
    int n = blockIdx.y;
    float v;
    if (n < RR * HD) v = W2[((size_t)(n >> 7) * HD + k) * HD + (n & 127)];
    else             v = root2[(size_t)k * HD + (n - RR * HD)];
    g_Bth[(size_t)n * HD + k] = __float2half_rn(v);
}

// ---------------- graph / misc kernels ------------------------------------------
__global__ void zero_f(float* p, int n) {
    int i = blockIdx.x * 256 + threadIdx.x;
    if (i < n) p[i] = 0.f;
}
__global__ void zero_i(int* p, int n) {
    int i = blockIdx.x * 256 + threadIdx.x;
    if (i < n) p[i] = 0;
}
__global__ void count_edges(const int* __restrict__ ei, const int* __restrict__ et) {
    int e = blockIdx.x * 256 + threadIdx.x;
    if (e < NE) atomicAdd(&g_cnt[ei[NE + e] * RR + et[e]], 1);
}
__global__ void scatter_agg(const float* __restrict__ Y,
                            const int* __restrict__ ei, const int* __restrict__ et) {
    int idx = blockIdx.x * 256 + threadIdx.x;
    if (idx >= NE * HD) return;
    int e = idx >> 7, hh = idx & 127;
    int src = ei[e];
    int dst = ei[NE + e];
    int r = et[e];
    float v = Y[(size_t)src * NCOLS + r * HD + hh];
    atomicAdd(&g_agg[((size_t)dst * RR + r) * HD + hh], v);
}
__global__ void combine1(const float* __restrict__ b1) {
    int idx = blockIdx.x * 256 + threadIdx.x;
    int n = idx >> 7, hh = idx & 127;
    float v = b1[hh] + g_Y[(size_t)n * NCOLS + RR * HD + hh];
#pragma unroll
    for (int r = 0; r < RR; r++) {
        float c = (float)g_cnt[n * RR + r];
        v += g_agg[((size_t)n * RR + r) * HD + hh] / fmaxf(c, 1.f);
    }
    g_h[idx] = v;
}
__global__ void softmax_s(const float* __restrict__ lin_w, const float* __restrict__ lin_b) {
    int n = blockIdx.x;
    int t = threadIdx.x;  // 128
    float hv = g_h[n * HD + t];
    float p0 = hv * lin_w[t * GGRP + 0];
    float p1 = hv * lin_w[t * GGRP + 1];
    float p2 = hv * lin_w[t * GGRP + 2];
#pragma unroll
    for (int o = 16; o; o >>= 1) {
        p0 += __shfl_down_sync(0xffffffffu, p0, o);
        p1 += __shfl_down_sync(0xffffffffu, p1, o);
        p2 += __shfl_down_sync(0xffffffffu, p2, o);
    }
    __shared__ float sm[4][3];
    if ((t & 31) == 0) { sm[t >> 5][0] = p0; sm[t >> 5][1] = p1; sm[t >> 5][2] = p2; }
    __syncthreads();
    if (t == 0) {
        float l0 = lin_b[0], l1 = lin_b[1], l2 = lin_b[2];
        for (int w = 0; w < 4; w++) { l0 += sm[w][0]; l1 += sm[w][1]; l2 += sm[w][2]; }
        float mx = fmaxf(l0, fmaxf(l1, l2));
        float e0 = expf(l0 - mx), e1 = expf(l1 - mx), e2 = expf(l2 - mx);
        float inv = 1.f / (e0 + e1 + e2);
        g_s[n * 3 + 0] = e0 * inv;
        g_s[n * 3 + 1] = e1 * inv;
        g_s[n * 3 + 2] = e2 * inv;
    }
}
__global__ void stats_k() {
    int t = threadIdx.x;
    int chunk = blockIdx.x;
    float sum0 = 0, sum1 = 0, sum2 = 0, sq0 = 0, sq1 = 0, sq2 = 0;
    for (int i = 0; i < 32; i++) {
        int n = chunk * 32 + i;
        float hv = g_h[n * HD + t];
        float s0 = g_s[n * 3 + 0], s1 = g_s[n * 3 + 1], s2 = g_s[n * 3 + 2];
        float v0 = s0 * hv, v1 = s1 * hv, v2 = s2 * hv;
        sum0 += v0; sq0 += v0 * v0;
        sum1 += v1; sq1 += v1 * v1;
        sum2 += v2; sq2 += v2 * v2;
    }
    atomicAdd(&g_sum[0 * HD + t], sum0);
    atomicAdd(&g_sum[1 * HD + t], sum1);
    atomicAdd(&g_sum[2 * HD + t], sum2);
    atomicAdd(&g_sq[0 * HD + t], sq0);
    atomicAdd(&g_sq[1 * HD + t], sq1);
    atomicAdd(&g_sq[2 * HD + t], sq2);
}
__global__ void stats_final(const float* __restrict__ bn_w, const float* __restrict__ bn_b) {
    int i = blockIdx.x * 128 + threadIdx.x;
    if (i < GGRP * HD) {
        const float invN = 1.f / (float)NN;
        float mean = g_sum[i] * invN;
        float var = g_sq[i] * invN - mean * mean;
        float a = bn_w[i] / sqrtf(var + EPSN);
        g_a[i] = a;
        g_d[i] = bn_b[i] - mean * a;
    }
}
__global__ void h2_k() {
    int idx = blockIdx.x * 256 + threadIdx.x;
    int n = idx >> 7, hh = idx & 127;
    float hv = g_h[idx];
    float s0 = g_s[n * 3 + 0], s1 = g_s[n * 3 + 1], s2 = g_s[n * 3 + 2];
    float aa = s0 * g_a[hh] + s1 * g_a[HD + hh] + s2 * g_a[2 * HD + hh];
    float cc = g_d[hh] + g_d[HD + hh] + g_d[2 * HD + hh];
    float v = fmaxf(hv * (1.f + LAMDA * aa) + LAMDA * cc, 0.f);
    g_h2h[idx] = __float2half_rn(v);
}
__global__ void combine2(const float* __restrict__ b2, float* __restrict__ out) {
    int idx = blockIdx.x * 256 + threadIdx.x;
    int n = idx >> 7, hh = idx & 127;
    float v = b2[hh] + g_Y[(size_t)n * NCOLS + RR * HD + hh];
#pragma unroll
    for (int r = 0; r < RR; r++) {
        float c = (float)g_cnt[n * RR + r];
        v += g_agg[((size_t)n * RR + r) * HD + hh] / fmaxf(c, 1.f);
    }
    out[idx] = v;
}

// ---------------- launch --------------------------------------------------------
extern "C" void kernel_launch(void* const* d_in, const int* in_sizes, int n_in,
                              void* d_out, int out_size) {
    const float* x      = (const float*)d_in[0];
    const int*   ei     = (const int*)d_in[1];
    const int*   et     = (const int*)d_in[2];
    const float* W1     = (const float*)d_in[3];
    const float* root1  = (const float*)d_in[4];
    const float* b1     = (const float*)d_in[5];
    const float* lin_w  = (const float*)d_in[6];
    const float* lin_b  = (const float*)d_in[7];
    const float* bn_w   = (const float*)d_in[8];
    const float* bn_b   = (const float*)d_in[9];
    const float* W2     = (const float*)d_in[10];
    const float* root2  = (const float*)d_in[11];
    const float* b2     = (const float*)d_in[12];
    float* out = (float*)d_out;

    float *Yp, *aggp, *sump, *sqp;
    int* cntp;
    __half *Ahp, *Bthp, *h2hp;
    cudaGetSymbolAddress((void**)&Yp, g_Y);
    cudaGetSymbolAddress((void**)&aggp, g_agg);
    cudaGetSymbolAddress((void**)&cntp, g_cnt);
    cudaGetSymbolAddress((void**)&sump, g_sum);
    cudaGetSymbolAddress((void**)&sqp, g_sq);
    cudaGetSymbolAddress((void**)&Ahp, g_Ah);
    cudaGetSymbolAddress((void**)&Bthp, g_Bth);
    cudaGetSymbolAddress((void**)&h2hp, g_h2h);

    cudaFuncSetAttribute(gemm_hmma, cudaFuncAttributeMaxDynamicSharedMemorySize, GEMM_SMEM);

    const int AGG_N = NN * RR * HD;

    // zero scratch
    zero_f<<<(AGG_N + 255) / 256, 256>>>(aggp, AGG_N);
    zero_i<<<(NN * RR + 255) / 256, 256>>>(cntp, NN * RR);
    zero_f<<<2, 256>>>(sump, GGRP * HD);
    zero_f<<<2, 256>>>(sqp, GGRP * HD);

    count_edges<<<NE / 256, 256>>>(ei, et);

    // layer 1: Y1 = x @ [W1_r ... | root1]  (fp16 HMMA GEMM, fp32 accum)
    conv_x<<<(NN * FIN / 4) / 256, 256>>>(x);
    {
        dim3 g(FIN / 256, NCOLS);
        pack_Bt1<<<g, 256>>>(W1, root1);
    }
    {
        dim3 grid(NCOLS / BNT, NN / BMT);
        gemm_hmma<<<grid, 256, GEMM_SMEM>>>(Ahp, Bthp, Yp, FIN);
    }
    scatter_agg<<<(NE * HD) / 256, 256>>>(Yp, ei, et);
    combine1<<<(NN * HD) / 256, 256>>>(b1);

    // DiffGroupNorm + relu
    softmax_s<<<NN, 128>>>(lin_w, lin_b);
    stats_k<<<128, 128>>>();
    stats_final<<<3, 128>>>(bn_w, bn_b);
    h2_k<<<(NN * HD) / 256, 256>>>();

    // layer 2: Y2 = h2 @ [W2_r ... | root2]
    {
        dim3 g(1, NCOLS);
        pack_Bt2<<<g, 128>>>(W2, root2);
    }
    {
        dim3 grid(NCOLS / BNT, NN / BMT);
        gemm_hmma<<<grid, 256, GEMM_SMEM>>>(h2hp, Bthp, Yp, HD);
    }
    zero_f<<<(AGG_N + 255) / 256, 256>>>(aggp, AGG_N);
    scatter_agg<<<(NE * HD) / 256, 256>>>(Yp, ei, et);
    combine2<<<(NN * HD) / 256, 256>>>(b2, out);
}

// round 6
// speedup vs baseline: 4.0168x; 1.1918x over previous
#include <cuda_runtime.h>
#include <cuda_fp16.h>
#include <math.h>
#include <stdint.h>

#define NN 4096      // nodes
#define FIN 4096     // input features
#define HD 128       // hidden / emb
#define RR 8         // relations
#define GGRP 3       // groups
#define NE 65536     // edges
#define NCOLS 1152   // 8*128 + 128
#define LAMDA 0.01f
#define EPSN 1e-5f

// GEMM tiling
#define BMT 128
#define BNT 128
#define BKT 64
#define STG 2
#define STAGE_B (BMT * BKT * 2 + BNT * BKT * 2)   // 32768 bytes per stage
#define GEMM_SMEM (STG * STAGE_B + 128)            // ~64KB -> 2 CTAs/SM

// ---------------- scratch ------------------------------------------------------
__device__ __align__(16) __half g_Ah[(size_t)NN * FIN];      // x as fp16
__device__ __align__(16) __half g_Bth[(size_t)NCOLS * FIN];  // B^T packed [n, k] fp16
__device__ __align__(16) __half g_h2h[NN * HD];              // post-DGN+relu fp16
__device__ float g_Y[(size_t)NN * NCOLS];
__device__ int   g_cnt[NN * RR];
__device__ float g_invc[NN * RR];
__device__ float g_h[NN * HD];
__device__ float g_s[NN * GGRP];
__device__ float g_sum[GGRP * HD];
__device__ float g_sq[GGRP * HD];
__device__ float g_a[GGRP * HD];
__device__ float g_d[GGRP * HD];

// ---------------- PTX helpers --------------------------------------------------
__device__ __forceinline__ uint32_t smem_u32(const void* p) {
    uint32_t a;
    asm("{ .reg .u64 t; cvta.to.shared.u64 t, %1; cvt.u32.u64 %0, t; }" : "=r"(a) : "l"(p));
    return a;
}
__device__ __forceinline__ void cp16(uint32_t d, const void* s) {
    asm volatile("cp.async.cg.shared.global [%0], [%1], 16;" :: "r"(d), "l"(s));
}
__device__ __forceinline__ void ldsm4(uint32_t& r0, uint32_t& r1, uint32_t& r2, uint32_t& r3,
                                      uint32_t a) {
    asm volatile("ldmatrix.sync.aligned.m8n8.x4.shared.b16 {%0,%1,%2,%3}, [%4];"
        : "=r"(r0), "=r"(r1), "=r"(r2), "=r"(r3) : "r"(a));
}
__device__ __forceinline__ void mma16816(float* d, const uint32_t* a, uint32_t b0, uint32_t b1) {
    asm volatile("mma.sync.aligned.m16n8k16.row.col.f32.f16.f16.f32 "
        "{%0,%1,%2,%3}, {%4,%5,%6,%7}, {%8,%9}, {%0,%1,%2,%3};"
        : "+f"(d[0]), "+f"(d[1]), "+f"(d[2]), "+f"(d[3])
        : "r"(a[0]), "r"(a[1]), "r"(a[2]), "r"(a[3]), "r"(b0), "r"(b1));
}

// ---------------- HMMA GEMM: C[M,1152] = A[M,K]fp16 @ Bt[1152,K]fp16^T ----------
__global__ __launch_bounds__(256, 2) void gemm_hmma(
    const __half* __restrict__ A, const __half* __restrict__ Bt,
    float* __restrict__ C, int K)
{
    extern __shared__ char smem_raw[];
    uint32_t sb = (smem_u32(smem_raw) + 127u) & ~127u;
    const int tid = threadIdx.x;
    const int lane = tid & 31;
    const int w = tid >> 5;
    const int m0 = blockIdx.y * BMT;
    const int n0 = blockIdx.x * BNT;
    const int wm = (w >> 2) * 64;     // warp tile 64x32, 2x4 warp grid
    const int wn = (w & 3) * 32;
    const int T = K >> 6;

    const int r7 = lane & 7;
    const int mat01 = (lane >> 3) & 1;
    const int mat2 = (lane >> 4) & 1;

    float acc[4][4][4];
#pragma unroll
    for (int i = 0; i < 4; i++)
#pragma unroll
        for (int j = 0; j < 4; j++)
#pragma unroll
            for (int c = 0; c < 4; c++) acc[i][j][c] = 0.f;

    auto ld_stage = [&](int buf, int t) {
        uint32_t base = sb + buf * STAGE_B;
        int k0 = t << 6;
#pragma unroll
        for (int i = 0; i < 4; i++) {
            int idx = tid + i * 256;         // 1024 16B-units per operand tile
            int row = idx >> 3;
            int u = idx & 7;
            int su = u ^ (row & 7);
            cp16(base + row * 128 + su * 16,
                 A + (size_t)(m0 + row) * K + k0 + u * 8);
            cp16(base + BMT * BKT * 2 + row * 128 + su * 16,
                 Bt + (size_t)(n0 + row) * K + k0 + u * 8);
        }
    };

    ld_stage(0, 0);
    asm volatile("cp.async.commit_group;");

    for (int t = 0; t < T; t++) {
        int pf = t + 1;
        if (pf < T) {
            ld_stage(pf & 1, pf);
            asm volatile("cp.async.commit_group;");
            asm volatile("cp.async.wait_group 1;");
        } else {
            asm volatile("cp.async.wait_group 0;");
        }
        __syncthreads();     // stage t fully resident for all warps

        uint32_t Ab = sb + (t & 1) * STAGE_B;
        uint32_t Bb = Ab + BMT * BKT * 2;

#pragma unroll
        for (int ks = 0; ks < 4; ks++) {
            const int u = ks * 2 + mat2;
            const int su16 = ((u ^ r7) * 16);

            uint32_t a[4][4];
#pragma unroll
            for (int i = 0; i < 4; i++) {
                int mrow = wm + i * 16 + mat01 * 8 + r7;
                ldsm4(a[i][0], a[i][1], a[i][2], a[i][3], Ab + mrow * 128 + su16);
            }
            uint32_t b[2][4];
#pragma unroll
            for (int j2 = 0; j2 < 2; j2++) {
                int nrow = wn + j2 * 16 + mat01 * 8 + r7;
                ldsm4(b[j2][0], b[j2][1], b[j2][2], b[j2][3], Bb + nrow * 128 + su16);
            }
#pragma unroll
            for (int i = 0; i < 4; i++)
#pragma unroll
                for (int j = 0; j < 4; j++) {
                    mma16816(acc[i][j], a[i], b[j >> 1][j & 1], b[j >> 1][(j & 1) + 2]);
                }
        }
        __syncthreads();     // protect stage buffer before next prefetch overwrites
    }

    // epilogue: direct fp32 stores
#pragma unroll
    for (int i = 0; i < 4; i++)
#pragma unroll
        for (int j = 0; j < 4; j++) {
            int m = m0 + wm + i * 16 + (lane >> 2);
            int n = n0 + wn + j * 8 + (lane & 3) * 2;
            float* p = C + (size_t)m * NCOLS + n;
            float2 v0 = make_float2(acc[i][j][0], acc[i][j][1]);
            float2 v1 = make_float2(acc[i][j][2], acc[i][j][3]);
            *(float2*)p = v0;
            *(float2*)(p + (size_t)8 * NCOLS) = v1;
        }
}

// ---------------- conversion / packing -----------------------------------------
__global__ void conv_x(const float* __restrict__ x) {
    size_t i = (size_t)blockIdx.x * 256 + threadIdx.x;   // NN*FIN/4
    float4 v = ((const float4*)x)[i];
    __half2* dst = (__half2*)g_Ah;
    dst[i * 2 + 0] = __floats2half2_rn(v.x, v.y);
    dst[i * 2 + 1] = __floats2half2_rn(v.z, v.w);
}

// Bt1[n, k] = (n<1024) ? W1[n>>7][k][n&127] : root1[k][n-1024]
__global__ void pack_Bt1(const float* __restrict__ W1, const float* __restrict__ root1) {
    int k = blockIdx.x * 256 + threadIdx.x;
    int n = blockIdx.y;
    float v;
    if (n < RR * HD) v = W1[((size_t)(n >> 7) * FIN + k) * HD + (n & 127)];
    else             v = root1[(size_t)k * HD + (n - RR * HD)];
    g_Bth[(size_t)n * FIN + k] = __float2half_rn(v);
}

// Bt2[n, k] (stride HD)
__global__ void pack_Bt2(const float* __restrict__ W2, const float* __restrict__ root2) {
    int k = threadIdx.x;   // 0..127
    int n = blockIdx.y;
    float v;
    if (n < RR * HD) v = W2[((size_t)(n >> 7) * HD + k) * HD + (n & 127)];
    else             v = root2[(size_t)k * HD + (n - RR * HD)];
    g_Bth[(size_t)n * HD + k] = __float2half_rn(v);
}

// ---------------- graph / misc kernels ------------------------------------------
__global__ void zero_f(float* p, int n) {
    int i = blockIdx.x * 256 + threadIdx.x;
    if (i < n) p[i] = 0.f;
}
__global__ void zero_i(int* p, int n) {
    int i = blockIdx.x * 256 + threadIdx.x;
    if (i < n) p[i] = 0;
}
__global__ void count_edges(const int* __restrict__ ei, const int* __restrict__ et) {
    int e = blockIdx.x * 256 + threadIdx.x;
    if (e < NE) atomicAdd(&g_cnt[ei[NE + e] * RR + et[e]], 1);
}
__global__ void invc_k() {
    int i = blockIdx.x * 256 + threadIdx.x;
    if (i < NN * RR) g_invc[i] = 1.f / fmaxf((float)g_cnt[i], 1.f);
}
// dst[idx] = bias[h] + Y[n, root-part h]
__global__ void init_h(const float* __restrict__ bias, const float* __restrict__ Y,
                       float* __restrict__ dst) {
    int idx = blockIdx.x * 256 + threadIdx.x;  // NN*HD
    int n = idx >> 7, hh = idx & 127;
    dst[idx] = bias[hh] + Y[(size_t)n * NCOLS + RR * HD + hh];
}
// per-edge scaled scatter straight into dst feature rows
__global__ void scatter_direct(const float* __restrict__ Y,
                               const int* __restrict__ ei, const int* __restrict__ et,
                               float* __restrict__ dst_arr) {
    int idx = blockIdx.x * 256 + threadIdx.x;  // NE*32
    int e = idx >> 5, q = idx & 31;
    int src = ei[e];
    int d = ei[NE + e];
    int r = et[e];
    float ic = g_invc[d * RR + r];
    float4 v = *(const float4*)(Y + (size_t)src * NCOLS + r * HD + q * 4);
    float* p = dst_arr + (size_t)d * HD + q * 4;
    atomicAdd(p + 0, v.x * ic);
    atomicAdd(p + 1, v.y * ic);
    atomicAdd(p + 2, v.z * ic);
    atomicAdd(p + 3, v.w * ic);
}
__global__ void softmax_s(const float* __restrict__ lin_w, const float* __restrict__ lin_b) {
    int n = blockIdx.x;
    int t = threadIdx.x;  // 128
    float hv = g_h[n * HD + t];
    float p0 = hv * lin_w[t * GGRP + 0];
    float p1 = hv * lin_w[t * GGRP + 1];
    float p2 = hv * lin_w[t * GGRP + 2];
#pragma unroll
    for (int o = 16; o; o >>= 1) {
        p0 += __shfl_down_sync(0xffffffffu, p0, o);
        p1 += __shfl_down_sync(0xffffffffu, p1, o);
        p2 += __shfl_down_sync(0xffffffffu, p2, o);
    }
    __shared__ float sm[4][3];
    if ((t & 31) == 0) { sm[t >> 5][0] = p0; sm[t >> 5][1] = p1; sm[t >> 5][2] = p2; }
    __syncthreads();
    if (t == 0) {
        float l0 = lin_b[0], l1 = lin_b[1], l2 = lin_b[2];
        for (int w = 0; w < 4; w++) { l0 += sm[w][0]; l1 += sm[w][1]; l2 += sm[w][2]; }
        float mx = fmaxf(l0, fmaxf(l1, l2));
        float e0 = expf(l0 - mx), e1 = expf(l1 - mx), e2 = expf(l2 - mx);
        float inv = 1.f / (e0 + e1 + e2);
        g_s[n * 3 + 0] = e0 * inv;
        g_s[n * 3 + 1] = e1 * inv;
        g_s[n * 3 + 2] = e2 * inv;
    }
}
__global__ void stats_k() {
    int t = threadIdx.x;
    int chunk = blockIdx.x;
    float sum0 = 0, sum1 = 0, sum2 = 0, sq0 = 0, sq1 = 0, sq2 = 0;
    for (int i = 0; i < 32; i++) {
        int n = chunk * 32 + i;
        float hv = g_h[n * HD + t];
        float s0 = g_s[n * 3 + 0], s1 = g_s[n * 3 + 1], s2 = g_s[n * 3 + 2];
        float v0 = s0 * hv, v1 = s1 * hv, v2 = s2 * hv;
        sum0 += v0; sq0 += v0 * v0;
        sum1 += v1; sq1 += v1 * v1;
        sum2 += v2; sq2 += v2 * v2;
    }
    atomicAdd(&g_sum[0 * HD + t], sum0);
    atomicAdd(&g_sum[1 * HD + t], sum1);
    atomicAdd(&g_sum[2 * HD + t], sum2);
    atomicAdd(&g_sq[0 * HD + t], sq0);
    atomicAdd(&g_sq[1 * HD + t], sq1);
    atomicAdd(&g_sq[2 * HD + t], sq2);
}
__global__ void stats_final(const float* __restrict__ bn_w, const float* __restrict__ bn_b) {
    int i = blockIdx.x * 128 + threadIdx.x;
    if (i < GGRP * HD) {
        const float invN = 1.f / (float)NN;
        float mean = g_sum[i] * invN;
        float var = g_sq[i] * invN - mean * mean;
        float a = bn_w[i] / sqrtf(var + EPSN);
        g_a[i] = a;
        g_d[i] = bn_b[i] - mean * a;
    }
}
__global__ void h2_k() {
    int idx = blockIdx.x * 256 + threadIdx.x;
    int n = idx >> 7, hh = idx & 127;
    float hv = g_h[idx];
    float s0 = g_s[n * 3 + 0], s1 = g_s[n * 3 + 1], s2 = g_s[n * 3 + 2];
    float aa = s0 * g_a[hh] + s1 * g_a[HD + hh] + s2 * g_a[2 * HD + hh];
    float cc = g_d[hh] + g_d[HD + hh] + g_d[2 * HD + hh];
    float v = fmaxf(hv * (1.f + LAMDA * aa) + LAMDA * cc, 0.f);
    g_h2h[idx] = __float2half_rn(v);
}

// ---------------- launch --------------------------------------------------------
extern "C" void kernel_launch(void* const* d_in, const int* in_sizes, int n_in,
                              void* d_out, int out_size) {
    const float* x      = (const float*)d_in[0];
    const int*   ei     = (const int*)d_in[1];
    const int*   et     = (const int*)d_in[2];
    const float* W1     = (const float*)d_in[3];
    const float* root1  = (const float*)d_in[4];
    const float* b1     = (const float*)d_in[5];
    const float* lin_w  = (const float*)d_in[6];
    const float* lin_b  = (const float*)d_in[7];
    const float* bn_w   = (const float*)d_in[8];
    const float* bn_b   = (const float*)d_in[9];
    const float* W2     = (const float*)d_in[10];
    const float* root2  = (const float*)d_in[11];
    const float* b2     = (const float*)d_in[12];
    float* out = (float*)d_out;

    float *Yp, *sump, *sqp, *hp;
    int* cntp;
    __half *Ahp, *Bthp, *h2hp;
    cudaGetSymbolAddress((void**)&Yp, g_Y);
    cudaGetSymbolAddress((void**)&cntp, g_cnt);
    cudaGetSymbolAddress((void**)&sump, g_sum);
    cudaGetSymbolAddress((void**)&sqp, g_sq);
    cudaGetSymbolAddress((void**)&hp, g_h);
    cudaGetSymbolAddress((void**)&Ahp, g_Ah);
    cudaGetSymbolAddress((void**)&Bthp, g_Bth);
    cudaGetSymbolAddress((void**)&h2hp, g_h2h);

    cudaFuncSetAttribute(gemm_hmma, cudaFuncAttributeMaxDynamicSharedMemorySize, GEMM_SMEM);

    // zero scratch + counts
    zero_i<<<(NN * RR + 255) / 256, 256>>>(cntp, NN * RR);
    zero_f<<<2, 256>>>(sump, GGRP * HD);
    zero_f<<<2, 256>>>(sqp, GGRP * HD);
    count_edges<<<NE / 256, 256>>>(ei, et);
    invc_k<<<(NN * RR + 255) / 256, 256>>>();

    // layer 1: Y1 = x @ [W1_r ... | root1]  (fp16 HMMA GEMM, fp32 accum)
    conv_x<<<(NN * FIN / 4) / 256, 256>>>(x);
    {
        dim3 g(FIN / 256, NCOLS);
        pack_Bt1<<<g, 256>>>(W1, root1);
    }
    {
        dim3 grid(NCOLS / BNT, NN / BMT);
        gemm_hmma<<<grid, 256, GEMM_SMEM>>>(Ahp, Bthp, Yp, FIN);
    }
    init_h<<<(NN * HD) / 256, 256>>>(b1, Yp, hp);
    scatter_direct<<<(NE * 32) / 256, 256>>>(Yp, ei, et, hp);

    // DiffGroupNorm + relu
    softmax_s<<<NN, 128>>>(lin_w, lin_b);
    stats_k<<<128, 128>>>();
    stats_final<<<3, 128>>>(bn_w, bn_b);
    h2_k<<<(NN * HD) / 256, 256>>>();

    // layer 2: Y2 = h2 @ [W2_r ... | root2]
    {
        dim3 g(1, NCOLS);
        pack_Bt2<<<g, 128>>>(W2, root2);
    }
    {
        dim3 grid(NCOLS / BNT, NN / BMT);
        gemm_hmma<<<grid, 256, GEMM_SMEM>>>(h2hp, Bthp, Yp, HD);
    }
    init_h<<<(NN * HD) / 256, 256>>>(b2, Yp, out);
    scatter_direct<<<(NE * 32) / 256, 256>>>(Yp, ei, et, out);
}

// round 8
// speedup vs baseline: 4.1909x; 1.0433x over previous
#include <cuda_runtime.h>
#include <cuda_fp16.h>
#include <math.h>
#include <stdint.h>

#define NN 4096      // nodes
#define FIN 4096     // input features
#define HD 128       // hidden / emb
#define RR 8         // relations
#define GGRP 3       // groups
#define NE 65536     // edges
#define NCOLS 1152   // 8*128 + 128
#define LAMDA 0.01f
#define EPSN 1e-5f

// GEMM tiling
#define BMT 128
#define BNT 128
#define BKT 64
#define STG 2
#define STAGE_B (BMT * BKT * 2 + BNT * BKT * 2)   // 32768 bytes per stage
#define GEMM_SMEM (STG * STAGE_B + 128)            // ~64KB -> 2 CTAs/SM

// ---------------- scratch ------------------------------------------------------
__device__ __align__(16) __half g_Ah[(size_t)NN * FIN];      // x as fp16
__device__ __align__(16) __half g_Bth[(size_t)NCOLS * FIN];  // B^T packed [n, k] fp16
__device__ __align__(16) __half g_h2h[NN * HD];              // post-DGN+relu fp16
__device__ float g_Y[(size_t)NN * NCOLS];
__device__ int   g_cnt[NN * RR];
__device__ float g_invc[NN * RR];
__device__ float g_h[NN * HD];
__device__ float g_s[NN * GGRP];
__device__ float g_sum[GGRP * HD];
__device__ float g_sq[GGRP * HD];
__device__ float g_a[GGRP * HD];
__device__ float g_d[GGRP * HD];

// ---------------- PTX helpers --------------------------------------------------
__device__ __forceinline__ uint32_t smem_u32(const void* p) {
    uint32_t a;
    asm("{ .reg .u64 t; cvta.to.shared.u64 t, %1; cvt.u32.u64 %0, t; }" : "=r"(a) : "l"(p));
    return a;
}
__device__ __forceinline__ void cp16(uint32_t d, const void* s) {
    asm volatile("cp.async.cg.shared.global [%0], [%1], 16;" :: "r"(d), "l"(s));
}
__device__ __forceinline__ void ldsm4(uint32_t& r0, uint32_t& r1, uint32_t& r2, uint32_t& r3,
                                      uint32_t a) {
    asm volatile("ldmatrix.sync.aligned.m8n8.x4.shared.b16 {%0,%1,%2,%3}, [%4];"
        : "=r"(r0), "=r"(r1), "=r"(r2), "=r"(r3) : "r"(a));
}
__device__ __forceinline__ void mma16816(float* d, const uint32_t* a, uint32_t b0, uint32_t b1) {
    asm volatile("mma.sync.aligned.m16n8k16.row.col.f32.f16.f16.f32 "
        "{%0,%1,%2,%3}, {%4,%5,%6,%7}, {%8,%9}, {%0,%1,%2,%3};"
        : "+f"(d[0]), "+f"(d[1]), "+f"(d[2]), "+f"(d[3])
        : "r"(a[0]), "r"(a[1]), "r"(a[2]), "r"(a[3]), "r"(b0), "r"(b1));
}

// ---------------- HMMA GEMM: C[M,1152] = A[M,K]fp16 @ Bt[1152,K]fp16^T ----------
__global__ __launch_bounds__(256, 2) void gemm_hmma(
    const __half* __restrict__ A, const __half* __restrict__ Bt,
    float* __restrict__ C, int K)
{
    extern __shared__ char smem_raw[];
    uint32_t sb = (smem_u32(smem_raw) + 127u) & ~127u;
    const int tid = threadIdx.x;
    const int lane = tid & 31;
    const int w = tid >> 5;
    const int m0 = blockIdx.y * BMT;
    const int n0 = blockIdx.x * BNT;
    const int wm = (w >> 2) * 64;     // warp tile 64x32, 2x4 warp grid
    const int wn = (w & 3) * 32;
    const int T = K >> 6;

    const int r7 = lane & 7;
    const int mat01 = (lane >> 3) & 1;
    const int mat2 = (lane >> 4) & 1;

    float acc[4][4][4];
#pragma unroll
    for (int i = 0; i < 4; i++)
#pragma unroll
        for (int j = 0; j < 4; j++)
#pragma unroll
            for (int c = 0; c < 4; c++) acc[i][j][c] = 0.f;

    auto ld_stage = [&](int buf, int t) {
        uint32_t base = sb + buf * STAGE_B;
        int k0 = t << 6;
#pragma unroll
        for (int i = 0; i < 4; i++) {
            int idx = tid + i * 256;         // 1024 16B-units per operand tile
            int row = idx >> 3;
            int u = idx & 7;
            int su = u ^ (row & 7);
            cp16(base + row * 128 + su * 16,
                 A + (size_t)(m0 + row) * K + k0 + u * 8);
            cp16(base + BMT * BKT * 2 + row * 128 + su * 16,
                 Bt + (size_t)(n0 + row) * K + k0 + u * 8);
        }
    };

    ld_stage(0, 0);
    asm volatile("cp.async.commit_group;");

    for (int t = 0; t < T; t++) {
        asm volatile("cp.async.wait_group 0;");   // load of chunk t complete
        __syncthreads();   // all warps: chunk t visible AND chunk t-1 compute done

        int pf = t + 1;
        if (pf < T) {
            ld_stage(pf & 1, pf);                 // safe: buf (t+1)&1 == (t-1)&1, compute t-1 done
            asm volatile("cp.async.commit_group;");
        }

        uint32_t Ab = sb + (t & 1) * STAGE_B;
        uint32_t Bb = Ab + BMT * BKT * 2;

#pragma unroll
        for (int ks = 0; ks < 4; ks++) {
            const int u = ks * 2 + mat2;
            const int su16 = ((u ^ r7) * 16);

            uint32_t a[4][4];
#pragma unroll
            for (int i = 0; i < 4; i++) {
                int mrow = wm + i * 16 + mat01 * 8 + r7;
                ldsm4(a[i][0], a[i][1], a[i][2], a[i][3], Ab + mrow * 128 + su16);
            }
            uint32_t b[2][4];
#pragma unroll
            for (int j2 = 0; j2 < 2; j2++) {
                int nrow = wn + j2 * 16 + mat01 * 8 + r7;
                ldsm4(b[j2][0], b[j2][1], b[j2][2], b[j2][3], Bb + nrow * 128 + su16);
            }
#pragma unroll
            for (int i = 0; i < 4; i++)
#pragma unroll
                for (int j = 0; j < 4; j++) {
                    mma16816(acc[i][j], a[i], b[j >> 1][j & 1], b[j >> 1][(j & 1) + 2]);
                }
        }
    }

    // epilogue: direct fp32 stores
#pragma unroll
    for (int i = 0; i < 4; i++)
#pragma unroll
        for (int j = 0; j < 4; j++) {
            int m = m0 + wm + i * 16 + (lane >> 2);
            int n = n0 + wn + j * 8 + (lane & 3) * 2;
            float* p = C + (size_t)m * NCOLS + n;
            float2 v0 = make_float2(acc[i][j][0], acc[i][j][1]);
            float2 v1 = make_float2(acc[i][j][2], acc[i][j][3]);
            *(float2*)p = v0;
            *(float2*)(p + (size_t)8 * NCOLS) = v1;
        }
}

// ---------------- conversion / packing -----------------------------------------
__global__ void conv_x(const float* __restrict__ x) {
    size_t i = (size_t)blockIdx.x * 256 + threadIdx.x;   // NN*FIN/4
    float4 v = ((const float4*)x)[i];
    __half2* dst = (__half2*)g_Ah;
    dst[i * 2 + 0] = __floats2half2_rn(v.x, v.y);
    dst[i * 2 + 1] = __floats2half2_rn(v.z, v.w);
}

// Coalesced transpose pack: Bth[z*128 + h][k] = src[k][h]
// src = (z<8) ? W[z] : root, both laid out [K, HD] row-major.
// grid (K/32, HD/32, 9), block (32, 8). Reads coalesced over h, writes over k.
__global__ void pack_BtT(const float* __restrict__ W, const float* __restrict__ root, int K) {
    __shared__ float t[32][33];
    int z = blockIdx.z;
    const float* base = (z < RR) ? (W + (size_t)z * K * HD) : root;
    int k0 = blockIdx.x * 32, h0 = blockIdx.y * 32;
#pragma unroll
    for (int i = threadIdx.y; i < 32; i += 8)
        t[i][threadIdx.x] = base[(size_t)(k0 + i) * HD + h0 + threadIdx.x];
    __syncthreads();
#pragma unroll
    for (int i = threadIdx.y; i < 32; i += 8) {
        int n = z * HD + h0 + i;
        g_Bth[(size_t)n * K + k0 + threadIdx.x] = __float2half_rn(t[threadIdx.x][i]);
    }
}

// ---------------- graph / misc kernels ------------------------------------------
__global__ void zero_f(float* p, int n) {
    int i = blockIdx.x * 256 + threadIdx.x;
    if (i < n) p[i] = 0.f;
}
__global__ void zero_i(int* p, int n) {
    int i = blockIdx.x * 256 + threadIdx.x;
    if (i < n) p[i] = 0;
}
__global__ void count_edges(const int* __restrict__ ei, const int* __restrict__ et) {
    int e = blockIdx.x * 256 + threadIdx.x;
    if (e < NE) atomicAdd(&g_cnt[ei[NE + e] * RR + et[e]], 1);
}
__global__ void invc_k() {
    int i = blockIdx.x * 256 + threadIdx.x;
    if (i < NN * RR) g_invc[i] = 1.f / fmaxf((float)g_cnt[i], 1.f);
}
// dst[idx] = bias[h] + Y[n, root-part h]
__global__ void init_h(const float* __restrict__ bias, const float* __restrict__ Y,
                       float* __restrict__ dst) {
    int idx = blockIdx.x * 256 + threadIdx.x;  // NN*HD
    int n = idx >> 7, hh = idx & 127;
    dst[idx] = bias[hh] + Y[(size_t)n * NCOLS + RR * HD + hh];
}
// per-edge scaled scatter straight into dst feature rows
__global__ void scatter_direct(const float* __restrict__ Y,
                               const int* __restrict__ ei, const int* __restrict__ et,
                               float* __restrict__ dst_arr) {
    int idx = blockIdx.x * 256 + threadIdx.x;  // NE*32
    int e = idx >> 5, q = idx & 31;
    int src = ei[e];
    int d = ei[NE + e];
    int r = et[e];
    float ic = g_invc[d * RR + r];
    float4 v = *(const float4*)(Y + (size_t)src * NCOLS + r * HD + q * 4);
    float* p = dst_arr + (size_t)d * HD + q * 4;
    atomicAdd(p + 0, v.x * ic);
    atomicAdd(p + 1, v.y * ic);
    atomicAdd(p + 2, v.z * ic);
    atomicAdd(p + 3, v.w * ic);
}
__global__ void softmax_s(const float* __restrict__ lin_w, const float* __restrict__ lin_b) {
    int n = blockIdx.x;
    int t = threadIdx.x;  // 128
    float hv = g_h[n * HD + t];
    float p0 = hv * lin_w[t * GGRP + 0];
    float p1 = hv * lin_w[t * GGRP + 1];
    float p2 = hv * lin_w[t * GGRP + 2];
#pragma unroll
    for (int o = 16; o; o >>= 1) {
        p0 += __shfl_down_sync(0xffffffffu, p0, o);
        p1 += __shfl_down_sync(0xffffffffu, p1, o);
        p2 += __shfl_down_sync(0xffffffffu, p2, o);
    }
    __shared__ float sm[4][3];
    if ((t & 31) == 0) { sm[t >> 5][0] = p0; sm[t >> 5][1] = p1; sm[t >> 5][2] = p2; }
    __syncthreads();
    if (t == 0) {
        float l0 = lin_b[0], l1 = lin_b[1], l2 = lin_b[2];
        for (int w = 0; w < 4; w++) { l0 += sm[w][0]; l1 += sm[w][1]; l2 += sm[w][2]; }
        float mx = fmaxf(l0, fmaxf(l1, l2));
        float e0 = expf(l0 - mx), e1 = expf(l1 - mx), e2 = expf(l2 - mx);
        float inv = 1.f / (e0 + e1 + e2);
        g_s[n * 3 + 0] = e0 * inv;
        g_s[n * 3 + 1] = e1 * inv;
        g_s[n * 3 + 2] = e2 * inv;
    }
}
__global__ void stats_k() {
    int t = threadIdx.x;
    int chunk = blockIdx.x;
    float sum0 = 0, sum1 = 0, sum2 = 0, sq0 = 0, sq1 = 0, sq2 = 0;
    for (int i = 0; i < 32; i++) {
        int n = chunk * 32 + i;
        float hv = g_h[n * HD + t];
        float s0 = g_s[n * 3 + 0], s1 = g_s[n * 3 + 1], s2 = g_s[n * 3 + 2];
        float v0 = s0 * hv, v1 = s1 * hv, v2 = s2 * hv;
        sum0 += v0; sq0 += v0 * v0;
        sum1 += v1; sq1 += v1 * v1;
        sum2 += v2; sq2 += v2 * v2;
    }
    atomicAdd(&g_sum[0 * HD + t], sum0);
    atomicAdd(&g_sum[1 * HD + t], sum1);
    atomicAdd(&g_sum[2 * HD + t], sum2);
    atomicAdd(&g_sq[0 * HD + t], sq0);
    atomicAdd(&g_sq[1 * HD + t], sq1);
    atomicAdd(&g_sq[2 * HD + t], sq2);
}
__global__ void stats_final(const float* __restrict__ bn_w, const float* __restrict__ bn_b) {
    int i = blockIdx.x * 128 + threadIdx.x;
    if (i < GGRP * HD) {
        const float invN = 1.f / (float)NN;
        float mean = g_sum[i] * invN;
        float var = g_sq[i] * invN - mean * mean;
        float a = bn_w[i] / sqrtf(var + EPSN);
        g_a[i] = a;
        g_d[i] = bn_b[i] - mean * a;
    }
}
__global__ void h2_k() {
    int idx = blockIdx.x * 256 + threadIdx.x;
    int n = idx >> 7, hh = idx & 127;
    float hv = g_h[idx];
    float s0 = g_s[n * 3 + 0], s1 = g_s[n * 3 + 1], s2 = g_s[n * 3 + 2];
    float aa = s0 * g_a[hh] + s1 * g_a[HD + hh] + s2 * g_a[2 * HD + hh];
    float cc = g_d[hh] + g_d[HD + hh] + g_d[2 * HD + hh];
    float v = fmaxf(hv * (1.f + LAMDA * aa) + LAMDA * cc, 0.f);
    g_h2h[idx] = __float2half_rn(v);
}

// ---------------- launch --------------------------------------------------------
extern "C" void kernel_launch(void* const* d_in, const int* in_sizes, int n_in,
                              void* d_out, int out_size) {
    const float* x      = (const float*)d_in[0];
    const int*   ei     = (const int*)d_in[1];
    const int*   et     = (const int*)d_in[2];
    const float* W1     = (const float*)d_in[3];
    const float* root1  = (const float*)d_in[4];
    const float* b1     = (const float*)d_in[5];
    const float* lin_w  = (const float*)d_in[6];
    const float* lin_b  = (const float*)d_in[7];
    const float* bn_w   = (const float*)d_in[8];
    const float* bn_b   = (const float*)d_in[9];
    const float* W2     = (const float*)d_in[10];
    const float* root2  = (const float*)d_in[11];
    const float* b2     = (const float*)d_in[12];
    float* out = (float*)d_out;

    float *Yp, *sump, *sqp, *hp;
    int* cntp;
    __half *Ahp, *Bthp, *h2hp;
    cudaGetSymbolAddress((void**)&Yp, g_Y);
    cudaGetSymbolAddress((void**)&cntp, g_cnt);
    cudaGetSymbolAddress((void**)&sump, g_sum);
    cudaGetSymbolAddress((void**)&sqp, g_sq);
    cudaGetSymbolAddress((void**)&hp, g_h);
    cudaGetSymbolAddress((void**)&Ahp, g_Ah);
    cudaGetSymbolAddress((void**)&Bthp, g_Bth);
    cudaGetSymbolAddress((void**)&h2hp, g_h2h);

    cudaFuncSetAttribute(gemm_hmma, cudaFuncAttributeMaxDynamicSharedMemorySize, GEMM_SMEM);

    // zero scratch + counts
    zero_i<<<(NN * RR + 255) / 256, 256>>>(cntp, NN * RR);
    zero_f<<<2, 256>>>(sump, GGRP * HD);
    zero_f<<<2, 256>>>(sqp, GGRP * HD);
    count_edges<<<NE / 256, 256>>>(ei, et);
    invc_k<<<(NN * RR + 255) / 256, 256>>>();

    // layer 1: Y1 = x @ [W1_r ... | root1]  (fp16 HMMA GEMM, fp32 accum)
    conv_x<<<(NN * FIN / 4) / 256, 256>>>(x);
    {
        dim3 g(FIN / 32, HD / 32, RR + 1);
        pack_BtT<<<g, dim3(32, 8)>>>(W1, root1, FIN);
    }
    {
        dim3 grid(NCOLS / BNT, NN / BMT);
        gemm_hmma<<<grid, 256, GEMM_SMEM>>>(Ahp, Bthp, Yp, FIN);
    }
    init_h<<<(NN * HD) / 256, 256>>>(b1, Yp, hp);
    scatter_direct<<<(NE * 32) / 256, 256>>>(Yp, ei, et, hp);

    // DiffGroupNorm + relu
    softmax_s<<<NN, 128>>>(lin_w, lin_b);
    stats_k<<<128, 128>>>();
    stats_final<<<3, 128>>>(bn_w, bn_b);
    h2_k<<<(NN * HD) / 256, 256>>>();

    // layer 2: Y2 = h2 @ [W2_r ... | root2]
    {
        dim3 g(HD / 32, HD / 32, RR + 1);
        pack_BtT<<<g, dim3(32, 8)>>>(W2, root2, HD);
    }
    {
        dim3 grid(NCOLS / BNT, NN / BMT);
        gemm_hmma<<<grid, 256, GEMM_SMEM>>>(h2hp, Bthp, Yp, HD);
    }
    init_h<<<(NN * HD) / 256, 256>>>(b2, Yp, out);
    scatter_direct<<<(NE * 32) / 256, 256>>>(Yp, ei, et, out);
}